// round 13
// baseline (speedup 1.0000x reference)
#include <cuda_runtime.h>

// Problem constants (from reference): N=1048576 rows, H=128, B=1024 segments.
#define H_DIM 128
#define EPS 1e-12f

// Single persistent kernel, zero prep. Warp w owns a contiguous chunk of
// rows; segment ids are monotone within the chunk, so one binary search
// before the loop + an (almost never taken) increment per iteration replaces
// any row->segment table. d (*) summary is applied inline.
// 4 rows per warp per iteration; each 8-lane group owns one row. Lane g
// holds float4 columns {g, g+8, g+16, g+24}: four FULL 128B lines per
// warp-load. e-loads front-batched; summary/d/ptr are L1/L2-resident.
__global__ void __launch_bounds__(256, 6) sim_kernel(
    const float* __restrict__ emb,
    const float* __restrict__ summary,
    const int*   __restrict__ ptr,      // int32 (JAX x64 disabled)
    const float* __restrict__ dvec,
    const float* __restrict__ scale,
    float* __restrict__ out,
    int n_rows, int n_seg, int rows_per_warp)
{
    const int wid  = (blockIdx.x * blockDim.x + threadIdx.x) >> 5;
    const int lane = threadIdx.x & 31;
    const int g    = lane & 7;        // position within 8-lane row group
    const int rsub = lane >> 3;       // which of the warp's 4 rows

    const int start = wid * rows_per_warp;
    if (start >= n_rows) return;
    const int end = min(start + rows_per_warp, n_rows);

    const float sc = __ldg(scale);

    // This lane's row for the first iteration (all 8 lanes of a group agree).
    int row = start + rsub;
    int rowc = min(row, n_rows - 1);

    // One-time binary search: seg = first s with ptr[s+1] > rowc.
    // Runs before any streaming load; amortized over the whole chunk.
    int seg;
    {
        int lo = 0, hi = n_seg;
        while (lo < hi) {
            int mid = (lo + hi) >> 1;
            if (__ldg(&ptr[mid + 1]) > rowc) hi = mid; else lo = mid + 1;
        }
        seg = lo;
    }

    for (int base = start; base < end; base += 4, row += 4) {
        const bool valid = row < end;
        rowc = min(row, n_rows - 1);

        // Monotone segment advance: ~0.004 increments/iter on average.
        while (__ldg(&ptr[seg + 1]) <= rowc) seg++;

        const float4* e4 = reinterpret_cast<const float4*>(emb)     + (size_t)rowc * (H_DIM / 4);
        const float4* s4 = reinterpret_cast<const float4*>(summary) + (size_t)seg  * (H_DIM / 4);
        const float4* d4 = reinterpret_cast<const float4*>(dvec);

        // ---- all 4 streaming loads front-batched ----
        const float4 e0 = __ldcs(&e4[g]);
        const float4 e1 = __ldcs(&e4[8 + g]);
        const float4 e2 = __ldcs(&e4[16 + g]);
        const float4 e3 = __ldcs(&e4[24 + g]);

        // Self-dot (norm) — consumes e as it lands.
        float ds;
        ds = e0.x * e0.x;
        ds = fmaf(e0.y, e0.y, ds); ds = fmaf(e0.z, e0.z, ds); ds = fmaf(e0.w, e0.w, ds);
        ds = fmaf(e1.x, e1.x, ds); ds = fmaf(e1.y, e1.y, ds);
        ds = fmaf(e1.z, e1.z, ds); ds = fmaf(e1.w, e1.w, ds);
        ds = fmaf(e2.x, e2.x, ds); ds = fmaf(e2.y, e2.y, ds);
        ds = fmaf(e2.z, e2.z, ds); ds = fmaf(e2.w, e2.w, ds);
        ds = fmaf(e3.x, e3.x, ds); ds = fmaf(e3.y, e3.y, ds);
        ds = fmaf(e3.z, e3.z, ds); ds = fmaf(e3.w, e3.w, ds);

        // Weighted dot with d (*) summary[seg] — all cache hits, inline d.
        float dw;
        {
            const float4 s = __ldg(&s4[g]);
            const float4 d = __ldg(&d4[g]);
            dw = (e0.x * d.x) * s.x;
            dw = fmaf(e0.y * d.y, s.y, dw);
            dw = fmaf(e0.z * d.z, s.z, dw);
            dw = fmaf(e0.w * d.w, s.w, dw);
        }
        {
            const float4 s = __ldg(&s4[8 + g]);
            const float4 d = __ldg(&d4[8 + g]);
            dw = fmaf(e1.x * d.x, s.x, dw);
            dw = fmaf(e1.y * d.y, s.y, dw);
            dw = fmaf(e1.z * d.z, s.z, dw);
            dw = fmaf(e1.w * d.w, s.w, dw);
        }
        {
            const float4 s = __ldg(&s4[16 + g]);
            const float4 d = __ldg(&d4[16 + g]);
            dw = fmaf(e2.x * d.x, s.x, dw);
            dw = fmaf(e2.y * d.y, s.y, dw);
            dw = fmaf(e2.z * d.z, s.z, dw);
            dw = fmaf(e2.w * d.w, s.w, dw);
        }
        {
            const float4 s = __ldg(&s4[24 + g]);
            const float4 d = __ldg(&d4[24 + g]);
            dw = fmaf(e3.x * d.x, s.x, dw);
            dw = fmaf(e3.y * d.y, s.y, dw);
            dw = fmaf(e3.z * d.z, s.z, dw);
            dw = fmaf(e3.w * d.w, s.w, dw);
        }

        // Reduce within each 8-lane group (3 butterfly steps, both sums).
        #pragma unroll
        for (int off = 4; off > 0; off >>= 1) {
            ds += __shfl_xor_sync(0xFFFFFFFFu, ds, off);
            dw += __shfl_xor_sync(0xFFFFFFFFu, dw, off);
        }

        if (g == 0 && valid) {
            __stcs(&out[row], sc * __fdividef(dw, fmaxf(sqrtf(ds), EPS)));
        }
    }
}

extern "C" void kernel_launch(void* const* d_in, const int* in_sizes, int n_in,
                              void* d_out, int out_size)
{
    const float* emb     = (const float*)d_in[0];   // [N, H]
    const float* summary = (const float*)d_in[1];   // [B, H]
    const int*   ptr     = (const int*)d_in[2];     // [B+1] int32
    const float* dvec    = (const float*)d_in[3];   // [H]
    const float* scale   = (const float*)d_in[4];   // [1]
    float*       out     = (float*)d_out;           // [N]

    const int n_rows = in_sizes[0] / H_DIM;   // N
    const int n_seg  = in_sizes[2] - 1;       // B

    // Persistent grid: 6 blocks/SM, 8 warps/block.
    int dev = 0, sms = 148;
    cudaGetDevice(&dev);
    cudaDeviceGetAttribute(&sms, cudaDevAttrMultiProcessorCount, dev);
    const int blocks      = sms * 6;
    const int total_warps = blocks * 8;
    // Contiguous rows per warp, rounded up to a multiple of 4.
    int rows_per_warp = (n_rows + total_warps - 1) / total_warps;
    rows_per_warp = (rows_per_warp + 3) & ~3;

    sim_kernel<<<blocks, 256>>>(emb, summary, ptr, dvec, scale, out,
                                n_rows, n_seg, rows_per_warp);
}

// round 14
// speedup vs baseline: 1.1329x; 1.1329x over previous
#include <cuda_runtime.h>

// Problem constants (from reference): N=1048576 rows, H=128, B=1024 segments.
#define H_DIM 128
#define EPS 1e-12f
#define MAX_B 4096          // scratch sized generously vs B=1024
#define MAX_N (1 << 20)     // N = 1048576

// Precomputed w[s,h] = d[h] * summary[s,h]  (512KB for B=1024)
__device__ float g_wbuf[MAX_B * H_DIM];
// Precomputed row -> segment id (2MB for N=1M)
__device__ unsigned short g_seg[MAX_N];

// Balanced prep (no per-segment block skew):
//  - w fill: grid-stride float4 (32768 vector elements)
//  - seg fill: each thread owns 8 consecutive rows -> one binary search +
//    monotone advance, one uint4 store (8 x u16).
__global__ void __launch_bounds__(256) prep_kernel(
    const float* __restrict__ summary,
    const float* __restrict__ dvec,
    const int*   __restrict__ ptr,
    int n_rows, int n_seg, int w_total)
{
    const int t       = blockIdx.x * 256 + (int)threadIdx.x;
    const int n_thr   = gridDim.x * 256;

    // ---- w = d (*) summary, vectorized ----
    const float4* s4 = reinterpret_cast<const float4*>(summary);
    const float4* d4 = reinterpret_cast<const float4*>(dvec);
    float4*       w4 = reinterpret_cast<float4*>(g_wbuf);
    for (int i = t; i < w_total / 4; i += n_thr) {
        const float4 s = s4[i];
        const float4 d = d4[i & (H_DIM / 4 - 1)];
        w4[i] = make_float4(s.x * d.x, s.y * d.y, s.z * d.z, s.w * d.w);
    }

    // ---- seg table, 8 rows per thread ----
    const int r0 = t * 8;
    if (r0 < n_rows) {
        // binary search: seg = first s with ptr[s+1] > r0
        int lo = 0, hi = n_seg;
        while (lo < hi) {
            int mid = (lo + hi) >> 1;
            if (__ldg(&ptr[mid + 1]) > r0) hi = mid; else lo = mid + 1;
        }
        int seg = lo;

        if (r0 + 8 <= n_rows) {
            unsigned v[4];
            #pragma unroll
            for (int p = 0; p < 4; p++) {
                const int ra = r0 + 2 * p, rb = ra + 1;
                while (__ldg(&ptr[seg + 1]) <= ra) seg++;
                const unsigned sa = (unsigned)seg;
                while (__ldg(&ptr[seg + 1]) <= rb) seg++;
                v[p] = sa | ((unsigned)seg << 16);
            }
            reinterpret_cast<uint4*>(g_seg)[t] =
                make_uint4(v[0], v[1], v[2], v[3]);
        } else {
            for (int r = r0; r < n_rows; r++) {
                while (__ldg(&ptr[seg + 1]) <= r) seg++;
                g_seg[r] = (unsigned short)seg;
            }
        }
    }
}

// Persistent grid-stride streaming kernel (R10 body + L2 prefetch of the
// next iteration's emb lines). 4 rows per warp per iteration; each 8-lane
// group owns one row. Lane g holds float4 columns {g, g+8, g+16, g+24}:
// four FULL 128B lines per warp-load. e-loads front-batched; w loads L2 hits.
__global__ void __launch_bounds__(256, 6) sim_kernel(
    const float* __restrict__ emb,
    const float* __restrict__ scale,
    float* __restrict__ out,
    int n_rows, int stride_rows)
{
    const int wid  = (blockIdx.x * blockDim.x + threadIdx.x) >> 5;
    const int lane = threadIdx.x & 31;
    const int g    = lane & 7;        // position within 8-lane row group
    const int rsub = lane >> 3;       // which of the warp's 4 rows
    const float sc = __ldg(scale);

    for (int base = wid * 4; base < n_rows; base += stride_rows) {
        int row = base + rsub;
        const bool valid = row < n_rows;
        row = min(row, n_rows - 1);

        const int seg = (int)g_seg[row];

        const float4* e4 = reinterpret_cast<const float4*>(emb)    + (size_t)row * (H_DIM / 4);
        const float4* w4 = reinterpret_cast<const float4*>(g_wbuf) + (size_t)seg * (H_DIM / 4);

        // ---- all 4 streaming loads front-batched ----
        const float4 e0 = __ldcs(&e4[g]);
        const float4 e1 = __ldcs(&e4[8 + g]);
        const float4 e2 = __ldcs(&e4[16 + g]);
        const float4 e3 = __ldcs(&e4[24 + g]);

        // ---- prefetch next iteration's lines into L2 (lanes 0-3 of each
        // group: one prefetch per 128B line, 16 lines per warp total) ----
        {
            const int nb = base + stride_rows;
            if (nb < n_rows && g < 4) {
                const char* np = reinterpret_cast<const char*>(
                    emb + (size_t)(nb + rsub) * H_DIM) + g * 128;
                asm volatile("prefetch.global.L2 [%0];" :: "l"(np));
            }
        }

        // Self-dot (norm) — consumes e as it lands.
        float ds;
        ds = e0.x * e0.x;
        ds = fmaf(e0.y, e0.y, ds); ds = fmaf(e0.z, e0.z, ds); ds = fmaf(e0.w, e0.w, ds);
        ds = fmaf(e1.x, e1.x, ds); ds = fmaf(e1.y, e1.y, ds);
        ds = fmaf(e1.z, e1.z, ds); ds = fmaf(e1.w, e1.w, ds);
        ds = fmaf(e2.x, e2.x, ds); ds = fmaf(e2.y, e2.y, ds);
        ds = fmaf(e2.z, e2.z, ds); ds = fmaf(e2.w, e2.w, ds);
        ds = fmaf(e3.x, e3.x, ds); ds = fmaf(e3.y, e3.y, ds);
        ds = fmaf(e3.z, e3.z, ds); ds = fmaf(e3.w, e3.w, ds);

        // Weighted dot — one float4 of w live at a time (L1/L2 hits).
        float dw;
        {
            const float4 w = __ldg(&w4[g]);
            dw = e0.x * w.x;
            dw = fmaf(e0.y, w.y, dw); dw = fmaf(e0.z, w.z, dw); dw = fmaf(e0.w, w.w, dw);
        }
        {
            const float4 w = __ldg(&w4[8 + g]);
            dw = fmaf(e1.x, w.x, dw); dw = fmaf(e1.y, w.y, dw);
            dw = fmaf(e1.z, w.z, dw); dw = fmaf(e1.w, w.w, dw);
        }
        {
            const float4 w = __ldg(&w4[16 + g]);
            dw = fmaf(e2.x, w.x, dw); dw = fmaf(e2.y, w.y, dw);
            dw = fmaf(e2.z, w.z, dw); dw = fmaf(e2.w, w.w, dw);
        }
        {
            const float4 w = __ldg(&w4[24 + g]);
            dw = fmaf(e3.x, w.x, dw); dw = fmaf(e3.y, w.y, dw);
            dw = fmaf(e3.z, w.z, dw); dw = fmaf(e3.w, w.w, dw);
        }

        // Reduce within each 8-lane group (3 butterfly steps, both sums).
        #pragma unroll
        for (int off = 4; off > 0; off >>= 1) {
            ds += __shfl_xor_sync(0xFFFFFFFFu, ds, off);
            dw += __shfl_xor_sync(0xFFFFFFFFu, dw, off);
        }

        if (g == 0 && valid) {
            __stcs(&out[row], sc * __fdividef(dw, fmaxf(sqrtf(ds), EPS)));
        }
    }
}

extern "C" void kernel_launch(void* const* d_in, const int* in_sizes, int n_in,
                              void* d_out, int out_size)
{
    const float* emb     = (const float*)d_in[0];   // [N, H]
    const float* summary = (const float*)d_in[1];   // [B, H]
    const int*   ptr     = (const int*)d_in[2];     // [B+1] int32
    const float* dvec    = (const float*)d_in[3];   // [H]
    const float* scale   = (const float*)d_in[4];   // [1]
    float*       out     = (float*)d_out;           // [N]

    const int n_rows  = in_sizes[0] / H_DIM;   // N
    const int n_seg   = in_sizes[2] - 1;       // B
    const int w_total = in_sizes[1];           // B*H

    // Balanced prep: one thread per 8 rows.
    const int seg_threads = (n_rows + 7) / 8;
    const int prep_blocks = (seg_threads + 255) / 256;
    prep_kernel<<<prep_blocks, 256>>>(summary, dvec, ptr, n_rows, n_seg, w_total);

    // Persistent sim: 6 blocks/SM, 8 warps/block, 4 rows/warp/iter.
    int dev = 0, sms = 148;
    cudaGetDevice(&dev);
    cudaDeviceGetAttribute(&sms, cudaDevAttrMultiProcessorCount, dev);
    const int blocks      = sms * 6;
    const int stride_rows = blocks * 8 * 4;

    sim_kernel<<<blocks, 256>>>(emb, scale, out, n_rows, stride_rows);
}

// round 15
// speedup vs baseline: 1.1664x; 1.0296x over previous
#include <cuda_runtime.h>

// Problem constants (from reference): N=1048576 rows, H=128, B=1024 segments.
#define H_DIM 128
#define EPS 1e-12f
#define MAX_B 4096          // scratch sized generously vs B=1024
#define MAX_N (1 << 20)     // N = 1048576

// Precomputed w[s,h] = d[h] * summary[s,h]  (512KB for B=1024)
__device__ float g_wbuf[MAX_B * H_DIM];
// Precomputed row -> segment id (2MB for N=1M)
__device__ unsigned short g_seg[MAX_N];

// Balanced prep (no per-segment block skew):
//  - w fill: grid-stride float4
//  - seg fill: each thread owns 8 consecutive rows -> one binary search +
//    monotone advance, one uint4 store (8 x u16).
__global__ void __launch_bounds__(256) prep_kernel(
    const float* __restrict__ summary,
    const float* __restrict__ dvec,
    const int*   __restrict__ ptr,
    int n_rows, int n_seg, int w_total)
{
    const int t     = blockIdx.x * 256 + (int)threadIdx.x;
    const int n_thr = gridDim.x * 256;

    // ---- w = d (*) summary, vectorized ----
    const float4* s4 = reinterpret_cast<const float4*>(summary);
    const float4* d4 = reinterpret_cast<const float4*>(dvec);
    float4*       w4 = reinterpret_cast<float4*>(g_wbuf);
    for (int i = t; i < w_total / 4; i += n_thr) {
        const float4 s = s4[i];
        const float4 d = d4[i & (H_DIM / 4 - 1)];
        w4[i] = make_float4(s.x * d.x, s.y * d.y, s.z * d.z, s.w * d.w);
    }

    // ---- seg table, 8 rows per thread ----
    const int r0 = t * 8;
    if (r0 < n_rows) {
        // binary search: seg = first s with ptr[s+1] > r0
        int lo = 0, hi = n_seg;
        while (lo < hi) {
            int mid = (lo + hi) >> 1;
            if (__ldg(&ptr[mid + 1]) > r0) hi = mid; else lo = mid + 1;
        }
        int seg = lo;

        if (r0 + 8 <= n_rows) {
            unsigned v[4];
            #pragma unroll
            for (int p = 0; p < 4; p++) {
                const int ra = r0 + 2 * p, rb = ra + 1;
                while (__ldg(&ptr[seg + 1]) <= ra) seg++;
                const unsigned sa = (unsigned)seg;
                while (__ldg(&ptr[seg + 1]) <= rb) seg++;
                v[p] = sa | ((unsigned)seg << 16);
            }
            reinterpret_cast<uint4*>(g_seg)[t] =
                make_uint4(v[0], v[1], v[2], v[3]);
        } else {
            for (int r = r0; r < n_rows; r++) {
                while (__ldg(&ptr[seg + 1]) <= r) seg++;
                g_seg[r] = (unsigned short)seg;
            }
        }
    }
}

// Persistent grid-stride streaming kernel (exact R10 body — best measured:
// 79.8us @ 86.1% DRAM). PDL consumer: prologue overlaps prep; the grid
// dependency sync gates only the first g_seg / g_wbuf access.
// 4 rows per warp per iteration; each 8-lane group owns one row. Lane g
// holds float4 columns {g, g+8, g+16, g+24}: four FULL 128B lines per
// warp-load. e-loads front-batched; w loads are L1/L2 hits.
__global__ void __launch_bounds__(256, 6) sim_kernel(
    const float* __restrict__ emb,
    const float* __restrict__ scale,
    float* __restrict__ out,
    int n_rows, int stride_rows)
{
    const int wid  = (blockIdx.x * blockDim.x + threadIdx.x) >> 5;
    const int lane = threadIdx.x & 31;
    const int g    = lane & 7;        // position within 8-lane row group
    const int rsub = lane >> 3;       // which of the warp's 4 rows
    const float sc = __ldg(scale);    // independent of prep outputs

    // Wait for prep's g_seg / g_wbuf writes to be visible.
    cudaGridDependencySynchronize();

    for (int base = wid * 4; base < n_rows; base += stride_rows) {
        int row = base + rsub;
        const bool valid = row < n_rows;
        row = min(row, n_rows - 1);

        const int seg = (int)g_seg[row];

        const float4* e4 = reinterpret_cast<const float4*>(emb)    + (size_t)row * (H_DIM / 4);
        const float4* w4 = reinterpret_cast<const float4*>(g_wbuf) + (size_t)seg * (H_DIM / 4);

        // ---- all 4 streaming loads front-batched ----
        const float4 e0 = __ldcs(&e4[g]);
        const float4 e1 = __ldcs(&e4[8 + g]);
        const float4 e2 = __ldcs(&e4[16 + g]);
        const float4 e3 = __ldcs(&e4[24 + g]);

        // Self-dot (norm) — consumes e as it lands.
        float ds;
        ds = e0.x * e0.x;
        ds = fmaf(e0.y, e0.y, ds); ds = fmaf(e0.z, e0.z, ds); ds = fmaf(e0.w, e0.w, ds);
        ds = fmaf(e1.x, e1.x, ds); ds = fmaf(e1.y, e1.y, ds);
        ds = fmaf(e1.z, e1.z, ds); ds = fmaf(e1.w, e1.w, ds);
        ds = fmaf(e2.x, e2.x, ds); ds = fmaf(e2.y, e2.y, ds);
        ds = fmaf(e2.z, e2.z, ds); ds = fmaf(e2.w, e2.w, ds);
        ds = fmaf(e3.x, e3.x, ds); ds = fmaf(e3.y, e3.y, ds);
        ds = fmaf(e3.z, e3.z, ds); ds = fmaf(e3.w, e3.w, ds);

        // Weighted dot — one float4 of w live at a time (L1/L2 hits).
        float dw;
        {
            const float4 w = __ldg(&w4[g]);
            dw = e0.x * w.x;
            dw = fmaf(e0.y, w.y, dw); dw = fmaf(e0.z, w.z, dw); dw = fmaf(e0.w, w.w, dw);
        }
        {
            const float4 w = __ldg(&w4[8 + g]);
            dw = fmaf(e1.x, w.x, dw); dw = fmaf(e1.y, w.y, dw);
            dw = fmaf(e1.z, w.z, dw); dw = fmaf(e1.w, w.w, dw);
        }
        {
            const float4 w = __ldg(&w4[16 + g]);
            dw = fmaf(e2.x, w.x, dw); dw = fmaf(e2.y, w.y, dw);
            dw = fmaf(e2.z, w.z, dw); dw = fmaf(e2.w, w.w, dw);
        }
        {
            const float4 w = __ldg(&w4[24 + g]);
            dw = fmaf(e3.x, w.x, dw); dw = fmaf(e3.y, w.y, dw);
            dw = fmaf(e3.z, w.z, dw); dw = fmaf(e3.w, w.w, dw);
        }

        // Reduce within each 8-lane group (3 butterfly steps, both sums).
        #pragma unroll
        for (int off = 4; off > 0; off >>= 1) {
            ds += __shfl_xor_sync(0xFFFFFFFFu, ds, off);
            dw += __shfl_xor_sync(0xFFFFFFFFu, dw, off);
        }

        if (g == 0 && valid) {
            __stcs(&out[row], sc * __fdividef(dw, fmaxf(sqrtf(ds), EPS)));
        }
    }
}

extern "C" void kernel_launch(void* const* d_in, const int* in_sizes, int n_in,
                              void* d_out, int out_size)
{
    const float* emb     = (const float*)d_in[0];   // [N, H]
    const float* summary = (const float*)d_in[1];   // [B, H]
    const int*   ptr     = (const int*)d_in[2];     // [B+1] int32
    const float* dvec    = (const float*)d_in[3];   // [H]
    const float* scale   = (const float*)d_in[4];   // [1]
    float*       out     = (float*)d_out;           // [N]

    const int n_rows  = in_sizes[0] / H_DIM;   // N
    const int n_seg   = in_sizes[2] - 1;       // B
    const int w_total = in_sizes[1];           // B*H

    // Balanced prep: one thread per 8 rows.
    const int seg_threads = (n_rows + 7) / 8;
    const int prep_blocks = (seg_threads + 255) / 256;
    prep_kernel<<<prep_blocks, 256>>>(summary, dvec, ptr, n_rows, n_seg, w_total);

    // Persistent sim launched with PDL so its prologue overlaps prep.
    int dev = 0, sms = 148;
    cudaGetDevice(&dev);
    cudaDeviceGetAttribute(&sms, cudaDevAttrMultiProcessorCount, dev);
    const int blocks      = sms * 6;
    const int stride_rows = blocks * 8 * 4;   // 8 warps/block, 4 rows/warp/iter

    cudaLaunchConfig_t cfg = {};
    cfg.gridDim  = dim3((unsigned)blocks, 1, 1);
    cfg.blockDim = dim3(256, 1, 1);
    cfg.dynamicSmemBytes = 0;
    cfg.stream = 0;
    cudaLaunchAttribute attrs[1];
    attrs[0].id = cudaLaunchAttributeProgrammaticStreamSerialization;
    attrs[0].val.programmaticStreamSerializationAllowed = 1;
    cfg.attrs = attrs;
    cfg.numAttrs = 1;

    cudaLaunchKernelEx(&cfg, sim_kernel, emb, scale, out, n_rows, stride_rows);
}

// round 16
// speedup vs baseline: 1.1916x; 1.0217x over previous
#include <cuda_runtime.h>

// Problem constants (from reference): N=1048576 rows, H=128, B=1024 segments.
#define H_DIM 128
#define EPS 1e-12f
#define MAX_B 4096          // scratch sized generously vs B=1024
#define MAX_N (1 << 20)     // N = 1048576

// Precomputed w[s,h] = d[h] * summary[s,h]  (512KB for B=1024)
__device__ float g_wbuf[MAX_B * H_DIM];
// Precomputed row -> segment id (2MB for N=1M)
__device__ unsigned short g_seg[MAX_N];

// Balanced prep (no per-segment block skew):
//  - w fill: grid-stride float4
//  - seg fill: each thread owns 8 consecutive rows -> one binary search +
//    monotone advance, one uint4 store (8 x u16).
__global__ void __launch_bounds__(256) prep_kernel(
    const float* __restrict__ summary,
    const float* __restrict__ dvec,
    const int*   __restrict__ ptr,
    int n_rows, int n_seg, int w_total)
{
    const int t     = blockIdx.x * 256 + (int)threadIdx.x;
    const int n_thr = gridDim.x * 256;

    // ---- w = d (*) summary, vectorized ----
    const float4* s4 = reinterpret_cast<const float4*>(summary);
    const float4* d4 = reinterpret_cast<const float4*>(dvec);
    float4*       w4 = reinterpret_cast<float4*>(g_wbuf);
    for (int i = t; i < w_total / 4; i += n_thr) {
        const float4 s = s4[i];
        const float4 d = d4[i & (H_DIM / 4 - 1)];
        w4[i] = make_float4(s.x * d.x, s.y * d.y, s.z * d.z, s.w * d.w);
    }

    // ---- seg table, 8 rows per thread ----
    const int r0 = t * 8;
    if (r0 < n_rows) {
        // binary search: seg = first s with ptr[s+1] > r0
        int lo = 0, hi = n_seg;
        while (lo < hi) {
            int mid = (lo + hi) >> 1;
            if (__ldg(&ptr[mid + 1]) > r0) hi = mid; else lo = mid + 1;
        }
        int seg = lo;

        if (r0 + 8 <= n_rows) {
            unsigned v[4];
            #pragma unroll
            for (int p = 0; p < 4; p++) {
                const int ra = r0 + 2 * p, rb = ra + 1;
                while (__ldg(&ptr[seg + 1]) <= ra) seg++;
                const unsigned sa = (unsigned)seg;
                while (__ldg(&ptr[seg + 1]) <= rb) seg++;
                v[p] = sa | ((unsigned)seg << 16);
            }
            reinterpret_cast<uint4*>(g_seg)[t] =
                make_uint4(v[0], v[1], v[2], v[3]);
        } else {
            for (int r = r0; r < n_rows; r++) {
                while (__ldg(&ptr[seg + 1]) <= r) seg++;
                g_seg[r] = (unsigned short)seg;
            }
        }
    }
}

// Wave-based streaming kernel (R9 body — best wallclock). PDL consumer:
// rollout overlaps prep; the grid dependency sync gates only the first
// g_seg / g_wbuf access.
// 4 rows per warp; each 8-lane group owns one row. Lane g holds float4
// columns {g, g+8, g+16, g+24}: four FULL 128B lines per warp-load.
// All 4 e-loads front-batched (~32 regs -> 8 blocks/SM theoretical).
__global__ void __launch_bounds__(256, 8) sim_kernel(
    const float* __restrict__ emb,
    const float* __restrict__ scale,
    float* __restrict__ out,
    int n_rows)
{
    const int wid  = (blockIdx.x * blockDim.x + threadIdx.x) >> 5;
    const int lane = threadIdx.x & 31;
    const int g    = lane & 7;        // position within 8-lane row group
    const int rsub = lane >> 3;       // which of the warp's 4 rows

    int row = wid * 4 + rsub;
    const bool valid = row < n_rows;
    row = min(row, n_rows - 1);

    const float sc = __ldg(scale);    // independent of prep outputs

    // Wait for prep's g_seg / g_wbuf writes to be visible.
    cudaGridDependencySynchronize();

    const int seg = (int)g_seg[row];

    const float4* e4 = reinterpret_cast<const float4*>(emb)    + (size_t)row * (H_DIM / 4);
    const float4* w4 = reinterpret_cast<const float4*>(g_wbuf) + (size_t)seg * (H_DIM / 4);

    // ---- all 4 streaming loads front-batched ----
    const float4 e0 = __ldcs(&e4[g]);
    const float4 e1 = __ldcs(&e4[8 + g]);
    const float4 e2 = __ldcs(&e4[16 + g]);
    const float4 e3 = __ldcs(&e4[24 + g]);

    // Self-dot (norm) — consumes e as it lands.
    float ds;
    ds = e0.x * e0.x;
    ds = fmaf(e0.y, e0.y, ds); ds = fmaf(e0.z, e0.z, ds); ds = fmaf(e0.w, e0.w, ds);
    ds = fmaf(e1.x, e1.x, ds); ds = fmaf(e1.y, e1.y, ds);
    ds = fmaf(e1.z, e1.z, ds); ds = fmaf(e1.w, e1.w, ds);
    ds = fmaf(e2.x, e2.x, ds); ds = fmaf(e2.y, e2.y, ds);
    ds = fmaf(e2.z, e2.z, ds); ds = fmaf(e2.w, e2.w, ds);
    ds = fmaf(e3.x, e3.x, ds); ds = fmaf(e3.y, e3.y, ds);
    ds = fmaf(e3.z, e3.z, ds); ds = fmaf(e3.w, e3.w, ds);

    // Weighted dot — one float4 of w live at a time (L1/L2 hits).
    float dw;
    {
        const float4 w = __ldg(&w4[g]);
        dw = e0.x * w.x;
        dw = fmaf(e0.y, w.y, dw); dw = fmaf(e0.z, w.z, dw); dw = fmaf(e0.w, w.w, dw);
    }
    {
        const float4 w = __ldg(&w4[8 + g]);
        dw = fmaf(e1.x, w.x, dw); dw = fmaf(e1.y, w.y, dw);
        dw = fmaf(e1.z, w.z, dw); dw = fmaf(e1.w, w.w, dw);
    }
    {
        const float4 w = __ldg(&w4[16 + g]);
        dw = fmaf(e2.x, w.x, dw); dw = fmaf(e2.y, w.y, dw);
        dw = fmaf(e2.z, w.z, dw); dw = fmaf(e2.w, w.w, dw);
    }
    {
        const float4 w = __ldg(&w4[24 + g]);
        dw = fmaf(e3.x, w.x, dw); dw = fmaf(e3.y, w.y, dw);
        dw = fmaf(e3.z, w.z, dw); dw = fmaf(e3.w, w.w, dw);
    }

    // Reduce within each 8-lane group (3 butterfly steps, both sums).
    #pragma unroll
    for (int off = 4; off > 0; off >>= 1) {
        ds += __shfl_xor_sync(0xFFFFFFFFu, ds, off);
        dw += __shfl_xor_sync(0xFFFFFFFFu, dw, off);
    }

    if (g == 0 && valid) {
        __stcs(&out[row], sc * __fdividef(dw, fmaxf(sqrtf(ds), EPS)));
    }
}

extern "C" void kernel_launch(void* const* d_in, const int* in_sizes, int n_in,
                              void* d_out, int out_size)
{
    const float* emb     = (const float*)d_in[0];   // [N, H]
    const float* summary = (const float*)d_in[1];   // [B, H]
    const int*   ptr     = (const int*)d_in[2];     // [B+1] int32
    const float* dvec    = (const float*)d_in[3];   // [H]
    const float* scale   = (const float*)d_in[4];   // [1]
    float*       out     = (float*)d_out;           // [N]

    const int n_rows  = in_sizes[0] / H_DIM;   // N
    const int n_seg   = in_sizes[2] - 1;       // B
    const int w_total = in_sizes[1];           // B*H

    // Balanced prep: one thread per 8 rows.
    const int seg_threads = (n_rows + 7) / 8;
    const int prep_blocks = (seg_threads + 255) / 256;
    prep_kernel<<<prep_blocks, 256>>>(summary, dvec, ptr, n_rows, n_seg, w_total);

    // Wave-based sim: 4 rows/warp, 8 warps/block -> 32 rows/block.
    const int n_warps = (n_rows + 3) / 4;
    const int blocks  = (n_warps + 7) / 8;

    cudaLaunchConfig_t cfg = {};
    cfg.gridDim  = dim3((unsigned)blocks, 1, 1);
    cfg.blockDim = dim3(256, 1, 1);
    cfg.dynamicSmemBytes = 0;
    cfg.stream = 0;
    cudaLaunchAttribute attrs[1];
    attrs[0].id = cudaLaunchAttributeProgrammaticStreamSerialization;
    attrs[0].val.programmaticStreamSerializationAllowed = 1;
    cfg.attrs = attrs;
    cfg.numAttrs = 1;

    cudaLaunchKernelEx(&cfg, sim_kernel, emb, scale, out, n_rows);
}

// round 17
// speedup vs baseline: 1.1953x; 1.0031x over previous
#include <cuda_runtime.h>

// Problem constants (from reference): N=1048576 rows, H=128, B=1024 segments.
#define H_DIM 128
#define EPS 1e-12f
#define MAX_B 4096          // scratch sized generously vs B=1024
#define MAX_N (1 << 20)     // N = 1048576

// Precomputed w[s,h] = d[h] * summary[s,h]  (512KB for B=1024)
__device__ float g_wbuf[MAX_B * H_DIM];
// Precomputed row -> segment id (2MB for N=1M)
__device__ unsigned short g_seg[MAX_N];

// Balanced prep (no per-segment block skew):
//  - w fill: grid-stride float4
//  - seg fill: each thread owns 8 consecutive rows -> one binary search +
//    monotone advance, one uint4 store (8 x u16).
__global__ void __launch_bounds__(256) prep_kernel(
    const float* __restrict__ summary,
    const float* __restrict__ dvec,
    const int*   __restrict__ ptr,
    int n_rows, int n_seg, int w_total)
{
    const int t     = blockIdx.x * 256 + (int)threadIdx.x;
    const int n_thr = gridDim.x * 256;

    // ---- w = d (*) summary, vectorized ----
    const float4* s4 = reinterpret_cast<const float4*>(summary);
    const float4* d4 = reinterpret_cast<const float4*>(dvec);
    float4*       w4 = reinterpret_cast<float4*>(g_wbuf);
    for (int i = t; i < w_total / 4; i += n_thr) {
        const float4 s = s4[i];
        const float4 d = d4[i & (H_DIM / 4 - 1)];
        w4[i] = make_float4(s.x * d.x, s.y * d.y, s.z * d.z, s.w * d.w);
    }

    // ---- seg table, 8 rows per thread ----
    const int r0 = t * 8;
    if (r0 < n_rows) {
        // binary search: seg = first s with ptr[s+1] > r0
        int lo = 0, hi = n_seg;
        while (lo < hi) {
            int mid = (lo + hi) >> 1;
            if (__ldg(&ptr[mid + 1]) > r0) hi = mid; else lo = mid + 1;
        }
        int seg = lo;

        if (r0 + 8 <= n_rows) {
            unsigned v[4];
            #pragma unroll
            for (int p = 0; p < 4; p++) {
                const int ra = r0 + 2 * p, rb = ra + 1;
                while (__ldg(&ptr[seg + 1]) <= ra) seg++;
                const unsigned sa = (unsigned)seg;
                while (__ldg(&ptr[seg + 1]) <= rb) seg++;
                v[p] = sa | ((unsigned)seg << 16);
            }
            reinterpret_cast<uint4*>(g_seg)[t] =
                make_uint4(v[0], v[1], v[2], v[3]);
        } else {
            for (int r = r0; r < n_rows; r++) {
                while (__ldg(&ptr[seg + 1]) <= r) seg++;
                g_seg[r] = (unsigned short)seg;
            }
        }
    }
}

// Wave-based streaming kernel, PDL consumer. KEY ORDERING: the 4 streaming
// e-loads (independent of prep) are issued BEFORE cudaGridDependencySynchronize,
// so they fly during the prep tail; only the g_seg / g_wbuf consumers wait.
// 4 rows per warp; each 8-lane group owns one row. Lane g holds float4
// columns {g, g+8, g+16, g+24}: four FULL 128B lines per warp-load.
__global__ void __launch_bounds__(256, 8) sim_kernel(
    const float* __restrict__ emb,
    const float* __restrict__ scale,
    float* __restrict__ out,
    int n_rows)
{
    const int wid  = (blockIdx.x * blockDim.x + threadIdx.x) >> 5;
    const int lane = threadIdx.x & 31;
    const int g    = lane & 7;        // position within 8-lane row group
    const int rsub = lane >> 3;       // which of the warp's 4 rows

    int row = wid * 4 + rsub;
    const bool valid = row < n_rows;
    row = min(row, n_rows - 1);

    const float sc = __ldg(scale);    // input, independent of prep

    const float4* e4 = reinterpret_cast<const float4*>(emb) + (size_t)row * (H_DIM / 4);

    // ---- streaming e-loads issued BEFORE the grid dependency sync ----
    const float4 e0 = __ldcs(&e4[g]);
    const float4 e1 = __ldcs(&e4[8 + g]);
    const float4 e2 = __ldcs(&e4[16 + g]);
    const float4 e3 = __ldcs(&e4[24 + g]);

    // Self-dot (norm) — depends only on e; also runs before the sync.
    float ds;
    ds = e0.x * e0.x;
    ds = fmaf(e0.y, e0.y, ds); ds = fmaf(e0.z, e0.z, ds); ds = fmaf(e0.w, e0.w, ds);
    ds = fmaf(e1.x, e1.x, ds); ds = fmaf(e1.y, e1.y, ds);
    ds = fmaf(e1.z, e1.z, ds); ds = fmaf(e1.w, e1.w, ds);
    ds = fmaf(e2.x, e2.x, ds); ds = fmaf(e2.y, e2.y, ds);
    ds = fmaf(e2.z, e2.z, ds); ds = fmaf(e2.w, e2.w, ds);
    ds = fmaf(e3.x, e3.x, ds); ds = fmaf(e3.y, e3.y, ds);
    ds = fmaf(e3.z, e3.z, ds); ds = fmaf(e3.w, e3.w, ds);

    // Wait for prep's g_seg / g_wbuf writes to be visible.
    cudaGridDependencySynchronize();

    const int seg = (int)g_seg[row];
    const float4* w4 = reinterpret_cast<const float4*>(g_wbuf) + (size_t)seg * (H_DIM / 4);

    // Weighted dot — one float4 of w live at a time (L1/L2 hits).
    float dw;
    {
        const float4 w = __ldg(&w4[g]);
        dw = e0.x * w.x;
        dw = fmaf(e0.y, w.y, dw); dw = fmaf(e0.z, w.z, dw); dw = fmaf(e0.w, w.w, dw);
    }
    {
        const float4 w = __ldg(&w4[8 + g]);
        dw = fmaf(e1.x, w.x, dw); dw = fmaf(e1.y, w.y, dw);
        dw = fmaf(e1.z, w.z, dw); dw = fmaf(e1.w, w.w, dw);
    }
    {
        const float4 w = __ldg(&w4[16 + g]);
        dw = fmaf(e2.x, w.x, dw); dw = fmaf(e2.y, w.y, dw);
        dw = fmaf(e2.z, w.z, dw); dw = fmaf(e2.w, w.w, dw);
    }
    {
        const float4 w = __ldg(&w4[24 + g]);
        dw = fmaf(e3.x, w.x, dw); dw = fmaf(e3.y, w.y, dw);
        dw = fmaf(e3.z, w.z, dw); dw = fmaf(e3.w, w.w, dw);
    }

    // Reduce within each 8-lane group (3 butterfly steps, both sums).
    #pragma unroll
    for (int off = 4; off > 0; off >>= 1) {
        ds += __shfl_xor_sync(0xFFFFFFFFu, ds, off);
        dw += __shfl_xor_sync(0xFFFFFFFFu, dw, off);
    }

    if (g == 0 && valid) {
        __stcs(&out[row], sc * __fdividef(dw, fmaxf(sqrtf(ds), EPS)));
    }
}

extern "C" void kernel_launch(void* const* d_in, const int* in_sizes, int n_in,
                              void* d_out, int out_size)
{
    const float* emb     = (const float*)d_in[0];   // [N, H]
    const float* summary = (const float*)d_in[1];   // [B, H]
    const int*   ptr     = (const int*)d_in[2];     // [B+1] int32
    const float* dvec    = (const float*)d_in[3];   // [H]
    const float* scale   = (const float*)d_in[4];   // [1]
    float*       out     = (float*)d_out;           // [N]

    const int n_rows  = in_sizes[0] / H_DIM;   // N
    const int n_seg   = in_sizes[2] - 1;       // B
    const int w_total = in_sizes[1];           // B*H

    // Balanced prep: one thread per 8 rows.
    const int seg_threads = (n_rows + 7) / 8;
    const int prep_blocks = (seg_threads + 255) / 256;
    prep_kernel<<<prep_blocks, 256>>>(summary, dvec, ptr, n_rows, n_seg, w_total);

    // Wave-based sim: 4 rows/warp, 8 warps/block -> 32 rows/block.
    const int n_warps = (n_rows + 3) / 4;
    const int blocks  = (n_warps + 7) / 8;

    cudaLaunchConfig_t cfg = {};
    cfg.gridDim  = dim3((unsigned)blocks, 1, 1);
    cfg.blockDim = dim3(256, 1, 1);
    cfg.dynamicSmemBytes = 0;
    cfg.stream = 0;
    cudaLaunchAttribute attrs[1];
    attrs[0].id = cudaLaunchAttributeProgrammaticStreamSerialization;
    attrs[0].val.programmaticStreamSerializationAllowed = 1;
    cfg.attrs = attrs;
    cfg.numAttrs = 1;

    cudaLaunchKernelEx(&cfg, sim_kernel, emb, scale, out, n_rows);
}